// round 11
// baseline (speedup 1.0000x reference)
#include <cuda_runtime.h>
#include <cuda_fp16.h>
#include <math.h>

#define NN 100000
#define NB 5000
#define NE 3200000
#define SCAN_CHUNK 1024
#define SCAN_NBLK ((NN + SCAN_CHUNK - 1) / SCAN_CHUNK)   // 98

// ---- device scratch ----
__device__ __align__(16) __half g_h16[NN * 16];  // fp16 h rows, 32B/node (slot 15 = 0)
__device__ __align__(16) float g_agg[NN * 16];   // fp32 agg
__device__ float g_b[NN * 19];
__device__ __align__(8) int2 g_adj[NE];          // CSC: {src row, norm bits}, sorted by col
__device__ int   g_cnt[NN];
__device__ int   g_off[NN];
__device__ int   g_cursor[NN];
__device__ int   g_bsum[SCAN_NBLK];
__device__ float g_dinv[NN];
__device__ float g_d2[NN];       // 1/deg (deg = cnt+1)
__device__ float g_sum;
__device__ int   g_is64;

// ---- detect edge dtype + init counters ----
__global__ void k_init(const int* __restrict__ ewords) {
    int v = blockIdx.x * blockDim.x + threadIdx.x;
    if (v < NN) { g_cnt[v] = 0; g_cursor[v] = 0; }
    if (v == 0) {
        int nonzero = 0;
        for (int i = 0; i < 64; i++) nonzero |= ewords[2 * i + 1];
        g_is64 = (nonzero == 0) ? 1 : 0;
        g_sum = 0.0f;
    }
}

// ---- in-degree histogram over col (2 edges/thread, vector loads) ----
__global__ void k_deg(const void* __restrict__ edges) {
    int i = blockIdx.x * blockDim.x + threadIdx.x;
    if (i >= NE / 2) return;
    int c0, c1;
    if (g_is64) {
        longlong2 cc = ((const longlong2*)edges)[NE / 2 + i];
        c0 = (int)cc.x; c1 = (int)cc.y;
    } else {
        int2 cc = ((const int2*)edges)[NE / 2 + i];
        c0 = cc.x; c1 = cc.y;
    }
    if ((unsigned)c0 < (unsigned)NN) atomicAdd(&g_cnt[c0], 1);
    if ((unsigned)c1 < (unsigned)NN) atomicAdd(&g_cnt[c1], 1);
}

// ---- blocked exclusive scan of cnt -> off ----
__global__ void k_scan1() {
    __shared__ int s[SCAN_CHUNK];
    int i = blockIdx.x * SCAN_CHUNK + threadIdx.x;
    int v = (i < NN) ? g_cnt[i] : 0;
    s[threadIdx.x] = v;
    __syncthreads();
    for (int d = 1; d < SCAN_CHUNK; d <<= 1) {
        int t = (threadIdx.x >= d) ? s[threadIdx.x - d] : 0;
        __syncthreads();
        s[threadIdx.x] += t;
        __syncthreads();
    }
    if (i < NN) g_off[i] = s[threadIdx.x] - v;
    if (threadIdx.x == SCAN_CHUNK - 1) g_bsum[blockIdx.x] = s[SCAN_CHUNK - 1];
}

__global__ void k_scan2() {
    __shared__ int s[128];
    int tid = threadIdx.x;
    int v = (tid < SCAN_NBLK) ? g_bsum[tid] : 0;
    s[tid] = v;
    __syncthreads();
    for (int d = 1; d < 128; d <<= 1) {
        int t = (tid >= d) ? s[tid - d] : 0;
        __syncthreads();
        s[tid] += t;
        __syncthreads();
    }
    if (tid < SCAN_NBLK) g_bsum[tid] = s[tid] - v;
}

// ---- scan fixup + dinv/d2 ----
__global__ void k_scan3() {
    int i = blockIdx.x * blockDim.x + threadIdx.x;
    if (i >= NN) return;
    g_off[i] += g_bsum[i / SCAN_CHUNK];
    float d = (float)(g_cnt[i] + 1);
    g_dinv[i] = 1.0f / sqrtf(d);
    g_d2[i]   = 1.0f / d;
}

// ---- place edges into CSC (2 edges/thread, vector loads) ----
__global__ void k_place(const void* __restrict__ edges) {
    int i = blockIdx.x * blockDim.x + threadIdx.x;
    if (i >= NE / 2) return;
    int r0, r1, c0, c1;
    if (g_is64) {
        longlong2 rr = ((const longlong2*)edges)[i];
        longlong2 cc = ((const longlong2*)edges)[NE / 2 + i];
        r0 = (int)rr.x; r1 = (int)rr.y;
        c0 = (int)cc.x; c1 = (int)cc.y;
    } else {
        int2 rr = ((const int2*)edges)[i];
        int2 cc = ((const int2*)edges)[NE / 2 + i];
        r0 = rr.x; r1 = rr.y;
        c0 = cc.x; c1 = cc.y;
    }
    if ((unsigned)r0 >= (unsigned)NN) r0 = 0;
    if ((unsigned)r1 >= (unsigned)NN) r1 = 0;
    if ((unsigned)c0 >= (unsigned)NN) c0 = 0;
    if ((unsigned)c1 >= (unsigned)NN) c1 = 0;
    int p0 = atomicAdd(&g_cursor[c0], 1);
    int2 rec0; rec0.x = r0; rec0.y = __float_as_int(g_dinv[r0] * g_dinv[c0]);
    g_adj[g_off[c0] + p0] = rec0;
    int p1 = atomicAdd(&g_cursor[c1], 1);
    int2 rec1; rec1.x = r1; rec1.y = __float_as_int(g_dinv[r1] * g_dinv[c1]);
    g_adj[g_off[c1] + p1] = rec1;
}

// ---- b = [x1|x2t] W4^T + b4 ; agg0 = x1 W1^T + b1 - bg ----
__global__ void k_ab(const float* __restrict__ x1, const float* __restrict__ x2,
                     const float* __restrict__ W4, const float* __restrict__ b4,
                     const float* __restrict__ W1, const float* __restrict__ b1,
                     const float* __restrict__ bg) {
    __shared__ float sW4[19 * 19], sb4[19], sW1[15 * 15], sb1[15], sbg[15];
    for (int i = threadIdx.x; i < 19 * 19; i += blockDim.x) sW4[i] = W4[i];
    for (int i = threadIdx.x; i < 15 * 15; i += blockDim.x) sW1[i] = W1[i];
    if (threadIdx.x < 19) sb4[threadIdx.x] = b4[threadIdx.x];
    if (threadIdx.x < 15) { sb1[threadIdx.x] = b1[threadIdx.x]; sbg[threadIdx.x] = bg[threadIdx.x]; }
    __syncthreads();

    int v = blockIdx.x * blockDim.x + threadIdx.x;
    if (v >= NN) return;

    float in[19];
    const float* x1r = x1 + (size_t)v * 15;
#pragma unroll
    for (int k = 0; k < 15; k++) in[k] = x1r[k];
    const float* x2r = x2 + (size_t)(v % NB) * 4;
#pragma unroll
    for (int k = 0; k < 4; k++) in[15 + k] = x2r[k];

    float* brow = g_b + (size_t)v * 19;
#pragma unroll
    for (int j = 0; j < 19; j++) {
        float acc = sb4[j];
#pragma unroll
        for (int k = 0; k < 19; k++) acc = fmaf(sW4[j * 19 + k], in[k], acc);
        brow[j] = acc;
    }

    float* arow = g_agg + (size_t)v * 16;
#pragma unroll
    for (int i = 0; i < 15; i++) {
        float acc = sb1[i] - sbg[i];
#pragma unroll
        for (int k = 0; k < 15; k++) acc = fmaf(sW1[i * 15 + k], in[k], acc);
        arow[i] = acc;
    }
    arow[15] = 0.0f;
}

// ---- kernel H: a = relu(agg+bg); h = Wg [a;b] -> fp16 rows ----
__global__ void k_H(const float* __restrict__ Wg, const float* __restrict__ bg) {
    __shared__ float sWg[15 * 34], sbg[15];
    for (int i = threadIdx.x; i < 15 * 34; i += blockDim.x) sWg[i] = Wg[i];
    if (threadIdx.x < 15) sbg[threadIdx.x] = bg[threadIdx.x];
    __syncthreads();

    int v = blockIdx.x * blockDim.x + threadIdx.x;
    if (v >= NN) return;

    float a[15], bb[19];
    const float* arow = g_agg + (size_t)v * 16;
#pragma unroll
    for (int i = 0; i < 15; i++) a[i] = fmaxf(arow[i] + sbg[i], 0.0f);
    const float* brow = g_b + (size_t)v * 19;
#pragma unroll
    for (int j = 0; j < 19; j++) bb[j] = brow[j];

    __half* hrow = g_h16 + (size_t)v * 16;
#pragma unroll
    for (int o = 0; o < 15; o++) {
        float acc = 0.0f;
        const float* w = sWg + o * 34;
#pragma unroll
        for (int k = 0; k < 15; k++) acc = fmaf(w[k], a[k], acc);
#pragma unroll
        for (int k = 0; k < 19; k++) acc = fmaf(w[15 + k], bb[k], acc);
        hrow[o] = __float2half(acc);
    }
    hrow[15] = __float2half(0.0f);
}

// 8 halves (uint4) * w accumulated into a[8] as fp32
__device__ __forceinline__ void fma8(float* a, uint4 p, float w) {
    __half2 h0 = *reinterpret_cast<__half2*>(&p.x);
    __half2 h1 = *reinterpret_cast<__half2*>(&p.y);
    __half2 h2 = *reinterpret_cast<__half2*>(&p.z);
    __half2 h3 = *reinterpret_cast<__half2*>(&p.w);
    float2 f0 = __half22float2(h0);
    float2 f1 = __half22float2(h1);
    float2 f2 = __half22float2(h2);
    float2 f3 = __half22float2(h3);
    a[0] = fmaf(f0.x, w, a[0]); a[1] = fmaf(f0.y, w, a[1]);
    a[2] = fmaf(f1.x, w, a[2]); a[3] = fmaf(f1.y, w, a[3]);
    a[4] = fmaf(f2.x, w, a[4]); a[5] = fmaf(f2.y, w, a[5]);
    a[6] = fmaf(f3.x, w, a[6]); a[7] = fmaf(f3.y, w, a[7]);
}

// ---- gather: 2 threads/node, fp16 rows, LDG.128 gathers (16 edges/warp/instr) ----
__global__ void k_gather() {
    int v = blockIdx.x * 128 + (threadIdx.x >> 1);   // 256 threads = 128 nodes/block
    int t = threadIdx.x & 1;                         // 16B half of the 32B row
    if (v >= NN) return;

    int off = g_off[v];
    int cnt = g_cnt[v];
    const int2* __restrict__ ap = g_adj + off;
    const uint4* __restrict__ h16 = reinterpret_cast<const uint4*>(g_h16);

    float a0[8], a1[8];
    {
        uint4 s = h16[(size_t)v * 2 + t];
        float d2 = g_d2[v];
#pragma unroll
        for (int k = 0; k < 8; k++) a0[k] = 0.0f;
        fma8(a0, s, d2);                             // self loop
#pragma unroll
        for (int k = 0; k < 8; k++) a1[k] = 0.0f;
    }

    int j = 0;
    for (; j + 4 <= cnt; j += 4) {
        int2 e0 = __ldg(ap + j + 0);
        int2 e1 = __ldg(ap + j + 1);
        int2 e2 = __ldg(ap + j + 2);
        int2 e3 = __ldg(ap + j + 3);
        uint4 p0 = h16[(size_t)e0.x * 2 + t];
        uint4 p1 = h16[(size_t)e1.x * 2 + t];
        uint4 p2 = h16[(size_t)e2.x * 2 + t];
        uint4 p3 = h16[(size_t)e3.x * 2 + t];
        fma8(a0, p0, __int_as_float(e0.y));
        fma8(a1, p1, __int_as_float(e1.y));
        fma8(a0, p2, __int_as_float(e2.y));
        fma8(a1, p3, __int_as_float(e3.y));
    }
    for (; j < cnt; j++) {
        int2 e = __ldg(ap + j);
        fma8(a0, h16[(size_t)e.x * 2 + t], __int_as_float(e.y));
    }

    float4* out = reinterpret_cast<float4*>(g_agg) + (size_t)v * 4 + t * 2;
    out[0] = make_float4(a0[0] + a1[0], a0[1] + a1[1], a0[2] + a1[2], a0[3] + a1[3]);
    out[1] = make_float4(a0[4] + a1[4], a0[5] + a1[5], a0[6] + a1[6], a0[7] + a1[7]);
}

// ---- final: a = relu(agg+bg); sum_v W3 . [a;b] ----
__global__ void k_final(const float* __restrict__ W3, const float* __restrict__ bg) {
    __shared__ float sW3[34], sbg[15];
    __shared__ float warpsum[32];
    if (threadIdx.x < 34) sW3[threadIdx.x] = W3[threadIdx.x];
    if (threadIdx.x < 15) sbg[threadIdx.x] = bg[threadIdx.x];
    __syncthreads();

    int v = blockIdx.x * blockDim.x + threadIdx.x;
    float acc = 0.0f;
    if (v < NN) {
        const float* arow = g_agg + (size_t)v * 16;
#pragma unroll
        for (int i = 0; i < 15; i++) {
            float a = fmaxf(arow[i] + sbg[i], 0.0f);
            acc = fmaf(sW3[i], a, acc);
        }
        const float* brow = g_b + (size_t)v * 19;
#pragma unroll
        for (int j = 0; j < 19; j++) acc = fmaf(sW3[15 + j], brow[j], acc);
    }
#pragma unroll
    for (int off = 16; off > 0; off >>= 1)
        acc += __shfl_down_sync(0xFFFFFFFFu, acc, off);
    int lane = threadIdx.x & 31, wid = threadIdx.x >> 5;
    if (lane == 0) warpsum[wid] = acc;
    __syncthreads();
    if (wid == 0) {
        int nwarps = (blockDim.x + 31) >> 5;
        float s = (lane < nwarps) ? warpsum[lane] : 0.0f;
#pragma unroll
        for (int off = 16; off > 0; off >>= 1)
            s += __shfl_down_sync(0xFFFFFFFFu, s, off);
        if (lane == 0) atomicAdd(&g_sum, s);
    }
}

__global__ void k_out(const float* __restrict__ b3, float* __restrict__ out) {
    out[0] = tanhf(g_sum / (float)NN + b3[0]);
}

extern "C" void kernel_launch(void* const* d_in, const int* in_sizes, int n_in,
                              void* d_out, int out_size) {
    const float* x1    = (const float*)d_in[0];
    const float* x2    = (const float*)d_in[1];
    const void*  edges = d_in[2];
    const float* W1    = (const float*)d_in[3];
    const float* b1    = (const float*)d_in[4];
    const float* Wg    = (const float*)d_in[5];
    const float* bg    = (const float*)d_in[6];
    const float* W3    = (const float*)d_in[7];
    const float* b3    = (const float*)d_in[8];
    const float* W4    = (const float*)d_in[9];
    const float* b4    = (const float*)d_in[10];
    float* out = (float*)d_out;

    const int TB = 256;
    const int gN  = (NN + TB - 1) / TB;
    const int gE2 = (NE / 2 + TB - 1) / TB;
    const int gG  = (NN + 127) / 128;   // 2 threads/node, 128 nodes/block

    k_init<<<gN, TB>>>((const int*)edges);
    k_deg<<<gE2, TB>>>(edges);
    k_scan1<<<SCAN_NBLK, SCAN_CHUNK>>>();
    k_scan2<<<1, 128>>>();
    k_scan3<<<gN, TB>>>();
    k_place<<<gE2, TB>>>(edges);
    k_ab<<<gN, TB>>>(x1, x2, W4, b4, W1, b1, bg);
    for (int it = 0; it < 5; it++) {
        k_H<<<gN, TB>>>(Wg, bg);
        k_gather<<<gG, TB>>>();
    }
    k_final<<<gN, TB>>>(W3, bg);
    k_out<<<1, 1>>>(b3, out);
}

// round 12
// speedup vs baseline: 1.3214x; 1.3214x over previous
#include <cuda_runtime.h>
#include <math.h>

#define NN 100000
#define NB 5000
#define NE 3200000
#define SCAN_CHUNK 1024
#define SCAN_NBLK ((NN + SCAN_CHUNK - 1) / SCAN_CHUNK)   // 98

// ---- device scratch ----
__device__ __align__(16) float g_h[NN * 16];    // padded h rows (slot 15 = 0)
__device__ __align__(16) float g_agg[NN * 16];  // padded agg
__device__ float g_b[NN * 19];
__device__ __align__(8) int2 g_adj[NE];         // CSC: {src row, norm bits}, sorted by col
__device__ int   g_cnt[NN];
__device__ int   g_off[NN];
__device__ int   g_cursor[NN];
__device__ int   g_bsum[SCAN_NBLK];
__device__ float g_dinv[NN];
__device__ float g_d2[NN];       // 1/deg (deg = cnt+1)
__device__ float g_sum;
__device__ int   g_is64;

// ---- detect edge dtype + init counters ----
__global__ void k_init(const int* __restrict__ ewords) {
    int v = blockIdx.x * blockDim.x + threadIdx.x;
    if (v < NN) { g_cnt[v] = 0; g_cursor[v] = 0; }
    if (v == 0) {
        int nonzero = 0;
        for (int i = 0; i < 64; i++) nonzero |= ewords[2 * i + 1];
        g_is64 = (nonzero == 0) ? 1 : 0;
        g_sum = 0.0f;
    }
}

// ---- in-degree histogram over col (2 edges/thread, vector loads) ----
__global__ void k_deg(const void* __restrict__ edges) {
    int i = blockIdx.x * blockDim.x + threadIdx.x;
    if (i >= NE / 2) return;
    int c0, c1;
    if (g_is64) {
        longlong2 cc = ((const longlong2*)edges)[NE / 2 + i];
        c0 = (int)cc.x; c1 = (int)cc.y;
    } else {
        int2 cc = ((const int2*)edges)[NE / 2 + i];
        c0 = cc.x; c1 = cc.y;
    }
    if ((unsigned)c0 < (unsigned)NN) atomicAdd(&g_cnt[c0], 1);
    if ((unsigned)c1 < (unsigned)NN) atomicAdd(&g_cnt[c1], 1);
}

// ---- blocked exclusive scan of cnt -> off ----
__global__ void k_scan1() {
    __shared__ int s[SCAN_CHUNK];
    int i = blockIdx.x * SCAN_CHUNK + threadIdx.x;
    int v = (i < NN) ? g_cnt[i] : 0;
    s[threadIdx.x] = v;
    __syncthreads();
    for (int d = 1; d < SCAN_CHUNK; d <<= 1) {
        int t = (threadIdx.x >= d) ? s[threadIdx.x - d] : 0;
        __syncthreads();
        s[threadIdx.x] += t;
        __syncthreads();
    }
    if (i < NN) g_off[i] = s[threadIdx.x] - v;
    if (threadIdx.x == SCAN_CHUNK - 1) g_bsum[blockIdx.x] = s[SCAN_CHUNK - 1];
}

__global__ void k_scan2() {
    __shared__ int s[128];
    int tid = threadIdx.x;
    int v = (tid < SCAN_NBLK) ? g_bsum[tid] : 0;
    s[tid] = v;
    __syncthreads();
    for (int d = 1; d < 128; d <<= 1) {
        int t = (tid >= d) ? s[tid - d] : 0;
        __syncthreads();
        s[tid] += t;
        __syncthreads();
    }
    if (tid < SCAN_NBLK) g_bsum[tid] = s[tid] - v;
}

// ---- scan fixup + dinv/d2 ----
__global__ void k_scan3() {
    int i = blockIdx.x * blockDim.x + threadIdx.x;
    if (i >= NN) return;
    g_off[i] += g_bsum[i / SCAN_CHUNK];
    float d = (float)(g_cnt[i] + 1);
    g_dinv[i] = 1.0f / sqrtf(d);
    g_d2[i]   = 1.0f / d;
}

// ---- place edges into CSC (2 edges/thread, vector loads) ----
__global__ void k_place(const void* __restrict__ edges) {
    int i = blockIdx.x * blockDim.x + threadIdx.x;
    if (i >= NE / 2) return;
    int r0, r1, c0, c1;
    if (g_is64) {
        longlong2 rr = ((const longlong2*)edges)[i];
        longlong2 cc = ((const longlong2*)edges)[NE / 2 + i];
        r0 = (int)rr.x; r1 = (int)rr.y;
        c0 = (int)cc.x; c1 = (int)cc.y;
    } else {
        int2 rr = ((const int2*)edges)[i];
        int2 cc = ((const int2*)edges)[NE / 2 + i];
        r0 = rr.x; r1 = rr.y;
        c0 = cc.x; c1 = cc.y;
    }
    if ((unsigned)r0 >= (unsigned)NN) r0 = 0;
    if ((unsigned)r1 >= (unsigned)NN) r1 = 0;
    if ((unsigned)c0 >= (unsigned)NN) c0 = 0;
    if ((unsigned)c1 >= (unsigned)NN) c1 = 0;
    int p0 = atomicAdd(&g_cursor[c0], 1);
    int2 rec0; rec0.x = r0; rec0.y = __float_as_int(g_dinv[r0] * g_dinv[c0]);
    g_adj[g_off[c0] + p0] = rec0;
    int p1 = atomicAdd(&g_cursor[c1], 1);
    int2 rec1; rec1.x = r1; rec1.y = __float_as_int(g_dinv[r1] * g_dinv[c1]);
    g_adj[g_off[c1] + p1] = rec1;
}

// ---- b = [x1|x2t] W4^T + b4 ; agg0 = x1 W1^T + b1 - bg ----
__global__ void k_ab(const float* __restrict__ x1, const float* __restrict__ x2,
                     const float* __restrict__ W4, const float* __restrict__ b4,
                     const float* __restrict__ W1, const float* __restrict__ b1,
                     const float* __restrict__ bg) {
    __shared__ float sW4[19 * 19], sb4[19], sW1[15 * 15], sb1[15], sbg[15];
    for (int i = threadIdx.x; i < 19 * 19; i += blockDim.x) sW4[i] = W4[i];
    for (int i = threadIdx.x; i < 15 * 15; i += blockDim.x) sW1[i] = W1[i];
    if (threadIdx.x < 19) sb4[threadIdx.x] = b4[threadIdx.x];
    if (threadIdx.x < 15) { sb1[threadIdx.x] = b1[threadIdx.x]; sbg[threadIdx.x] = bg[threadIdx.x]; }
    __syncthreads();

    int v = blockIdx.x * blockDim.x + threadIdx.x;
    if (v >= NN) return;

    float in[19];
    const float* x1r = x1 + (size_t)v * 15;
#pragma unroll
    for (int k = 0; k < 15; k++) in[k] = x1r[k];
    const float* x2r = x2 + (size_t)(v % NB) * 4;
#pragma unroll
    for (int k = 0; k < 4; k++) in[15 + k] = x2r[k];

    float* brow = g_b + (size_t)v * 19;
#pragma unroll
    for (int j = 0; j < 19; j++) {
        float acc = sb4[j];
#pragma unroll
        for (int k = 0; k < 19; k++) acc = fmaf(sW4[j * 19 + k], in[k], acc);
        brow[j] = acc;
    }

    float* arow = g_agg + (size_t)v * 16;
#pragma unroll
    for (int i = 0; i < 15; i++) {
        float acc = sb1[i] - sbg[i];
#pragma unroll
        for (int k = 0; k < 15; k++) acc = fmaf(sW1[i * 15 + k], in[k], acc);
        arow[i] = acc;
    }
    arow[15] = 0.0f;
}

// ---- kernel H: a = relu(agg+bg); h = Wg [a;b] ----
__global__ void k_H(const float* __restrict__ Wg, const float* __restrict__ bg) {
    __shared__ float sWg[15 * 34], sbg[15];
    for (int i = threadIdx.x; i < 15 * 34; i += blockDim.x) sWg[i] = Wg[i];
    if (threadIdx.x < 15) sbg[threadIdx.x] = bg[threadIdx.x];
    __syncthreads();

    int v = blockIdx.x * blockDim.x + threadIdx.x;
    if (v >= NN) return;

    float a[15], bb[19];
    const float* arow = g_agg + (size_t)v * 16;
#pragma unroll
    for (int i = 0; i < 15; i++) a[i] = fmaxf(arow[i] + sbg[i], 0.0f);
    const float* brow = g_b + (size_t)v * 19;
#pragma unroll
    for (int j = 0; j < 19; j++) bb[j] = brow[j];

    float* hrow = g_h + (size_t)v * 16;
#pragma unroll
    for (int o = 0; o < 15; o++) {
        float acc = 0.0f;
        const float* w = sWg + o * 34;
#pragma unroll
        for (int k = 0; k < 15; k++) acc = fmaf(w[k], a[k], acc);
#pragma unroll
        for (int k = 0; k < 19; k++) acc = fmaf(w[15 + k], bb[k], acc);
        hrow[o] = acc;
    }
    hrow[15] = 0.0f;
}

__device__ __forceinline__ float4 fma4(float4 p, float w, float4 a) {
    a.x = fmaf(p.x, w, a.x);
    a.y = fmaf(p.y, w, a.y);
    a.z = fmaf(p.z, w, a.z);
    a.w = fmaf(p.w, w, a.w);
    return a;
}

// ---- gather: one WARP per node; 8 lane-groups of 4 cover 8 edges/iter ----
__global__ void k_gather() {
    int v = (blockIdx.x * blockDim.x + threadIdx.x) >> 5;   // warp id = node
    if (v >= NN) return;
    int lane = threadIdx.x & 31;
    int g = lane >> 2;          // edge-slot group 0..7
    int t = lane & 3;           // float4 quarter of the 64B row

    int off = g_off[v];
    int cnt = g_cnt[v];
    const int2* __restrict__ ap = g_adj + off;
    const float4* __restrict__ h4 = reinterpret_cast<const float4*>(g_h);

    float4 acc = make_float4(0.f, 0.f, 0.f, 0.f);
    float4 ac1 = make_float4(0.f, 0.f, 0.f, 0.f);

    int j = g;
    for (; j + 8 < cnt; j += 16) {                 // 2-deep unroll for MLP
        int2 e0 = __ldg(ap + j);
        int2 e1 = __ldg(ap + j + 8);
        float4 p0 = h4[(size_t)e0.x * 4 + t];
        float4 p1 = h4[(size_t)e1.x * 4 + t];
        acc = fma4(p0, __int_as_float(e0.y), acc);
        ac1 = fma4(p1, __int_as_float(e1.y), ac1);
    }
    if (j < cnt) {
        int2 e = __ldg(ap + j);
        acc = fma4(h4[(size_t)e.x * 4 + t], __int_as_float(e.y), acc);
    }
    acc.x += ac1.x; acc.y += ac1.y; acc.z += ac1.z; acc.w += ac1.w;

    // reduce across the 8 groups (lanes differing in bits 2..4)
#pragma unroll
    for (int d = 4; d <= 16; d <<= 1) {
        acc.x += __shfl_xor_sync(0xFFFFFFFFu, acc.x, d);
        acc.y += __shfl_xor_sync(0xFFFFFFFFu, acc.y, d);
        acc.z += __shfl_xor_sync(0xFFFFFFFFu, acc.z, d);
        acc.w += __shfl_xor_sync(0xFFFFFFFFu, acc.w, d);
    }

    if (g == 0) {
        float d2 = g_d2[v];
        float4 s = h4[(size_t)v * 4 + t];          // self loop
        acc.x = fmaf(s.x, d2, acc.x);
        acc.y = fmaf(s.y, d2, acc.y);
        acc.z = fmaf(s.z, d2, acc.z);
        acc.w = fmaf(s.w, d2, acc.w);
        reinterpret_cast<float4*>(g_agg)[(size_t)v * 4 + t] = acc;
    }
}

// ---- final: a = relu(agg+bg); sum_v W3 . [a;b] ----
__global__ void k_final(const float* __restrict__ W3, const float* __restrict__ bg) {
    __shared__ float sW3[34], sbg[15];
    __shared__ float warpsum[32];
    if (threadIdx.x < 34) sW3[threadIdx.x] = W3[threadIdx.x];
    if (threadIdx.x < 15) sbg[threadIdx.x] = bg[threadIdx.x];
    __syncthreads();

    int v = blockIdx.x * blockDim.x + threadIdx.x;
    float acc = 0.0f;
    if (v < NN) {
        const float* arow = g_agg + (size_t)v * 16;
#pragma unroll
        for (int i = 0; i < 15; i++) {
            float a = fmaxf(arow[i] + sbg[i], 0.0f);
            acc = fmaf(sW3[i], a, acc);
        }
        const float* brow = g_b + (size_t)v * 19;
#pragma unroll
        for (int j = 0; j < 19; j++) acc = fmaf(sW3[15 + j], brow[j], acc);
    }
#pragma unroll
    for (int off = 16; off > 0; off >>= 1)
        acc += __shfl_down_sync(0xFFFFFFFFu, acc, off);
    int lane = threadIdx.x & 31, wid = threadIdx.x >> 5;
    if (lane == 0) warpsum[wid] = acc;
    __syncthreads();
    if (wid == 0) {
        int nwarps = (blockDim.x + 31) >> 5;
        float s = (lane < nwarps) ? warpsum[lane] : 0.0f;
#pragma unroll
        for (int off = 16; off > 0; off >>= 1)
            s += __shfl_down_sync(0xFFFFFFFFu, s, off);
        if (lane == 0) atomicAdd(&g_sum, s);
    }
}

__global__ void k_out(const float* __restrict__ b3, float* __restrict__ out) {
    out[0] = tanhf(g_sum / (float)NN + b3[0]);
}

extern "C" void kernel_launch(void* const* d_in, const int* in_sizes, int n_in,
                              void* d_out, int out_size) {
    const float* x1    = (const float*)d_in[0];
    const float* x2    = (const float*)d_in[1];
    const void*  edges = d_in[2];
    const float* W1    = (const float*)d_in[3];
    const float* b1    = (const float*)d_in[4];
    const float* Wg    = (const float*)d_in[5];
    const float* bg    = (const float*)d_in[6];
    const float* W3    = (const float*)d_in[7];
    const float* b3    = (const float*)d_in[8];
    const float* W4    = (const float*)d_in[9];
    const float* b4    = (const float*)d_in[10];
    float* out = (float*)d_out;

    const int TB = 256;
    const int gN  = (NN + TB - 1) / TB;
    const int gE2 = (NE / 2 + TB - 1) / TB;
    const int gG  = (NN * 32 + TB - 1) / TB;   // one warp per node

    k_init<<<gN, TB>>>((const int*)edges);
    k_deg<<<gE2, TB>>>(edges);
    k_scan1<<<SCAN_NBLK, SCAN_CHUNK>>>();
    k_scan2<<<1, 128>>>();
    k_scan3<<<gN, TB>>>();
    k_place<<<gE2, TB>>>(edges);
    k_ab<<<gN, TB>>>(x1, x2, W4, b4, W1, b1, bg);
    for (int it = 0; it < 5; it++) {
        k_H<<<gN, TB>>>(Wg, bg);
        k_gather<<<gG, TB>>>();
    }
    k_final<<<gN, TB>>>(W3, bg);
    k_out<<<1, 1>>>(b3, out);
}